// round 1
// baseline (speedup 1.0000x reference)
#include <cuda_runtime.h>

#define Bdim 4
#define Sdim 4096
#define Hdim 1024
#define Mtot (Bdim * Sdim)

// Scratch (device globals: allocation-free per harness rules)
__device__ float g_q[(size_t)Bdim * Sdim * Hdim];
__device__ float g_k[(size_t)Bdim * Sdim * Hdim];
__device__ float g_v[(size_t)Bdim * Sdim * Hdim];
__device__ float g_e[(size_t)Bdim * Sdim * Sdim];

// ---- packed f32x2 helpers (sm_103a: doubles fp32 FMA throughput vs FFMA-3reg) ----
__device__ __forceinline__ unsigned long long pack2(float lo, float hi) {
    unsigned long long r;
    asm("mov.b64 %0, {%1, %2};" : "=l"(r)
        : "r"(__float_as_uint(lo)), "r"(__float_as_uint(hi)));
    return r;
}
__device__ __forceinline__ void unpack2(unsigned long long v, float& lo, float& hi) {
    unsigned int a, b;
    asm("mov.b64 {%0, %1}, %2;" : "=r"(a), "=r"(b) : "l"(v));
    lo = __uint_as_float(a); hi = __uint_as_float(b);
}
__device__ __forceinline__ unsigned long long fma2(unsigned long long a,
                                                   unsigned long long b,
                                                   unsigned long long c) {
    unsigned long long d;
    asm("fma.rn.f32x2 %0, %1, %2, %3;" : "=l"(d) : "l"(a), "l"(b), "l"(c));
    return d;
}

// ---- generic tiled GEMM: C = scale * (A @ B[^T]) + bias ----
// A: M x K row-major.  NN: B is K x N row-major.  NT: B is N x K row-major (B^T used).
// Per-blockIdx.z batch strides sA/sB/sC. BM=BN=128, BK=16, 256 threads, 8x8/thread.
template <bool NT, bool HASBIAS>
__global__ __launch_bounds__(256, 2)
void gemm_kernel(const float* __restrict__ A, const float* __restrict__ Bm,
                 const float* __restrict__ bias, float* __restrict__ C,
                 int M, int N, int K,
                 long long sA, long long sB, long long sC, float scale)
{
    const int BM = 128, BN = 128, BK = 16;
    __shared__ float As[BK][BM];
    __shared__ float Bs[BK][BN];

    A  += (size_t)blockIdx.z * sA;
    Bm += (size_t)blockIdx.z * sB;
    C  += (size_t)blockIdx.z * sC;

    const int t  = threadIdx.x;
    const int tx = t & 15;        // 0..15 -> N direction (8 cols each)
    const int ty = t >> 4;        // 0..15 -> M direction (8 rows each)
    const int m0 = blockIdx.y * BM;
    const int n0 = blockIdx.x * BN;

    // A-tile (and NT B-tile) load indices: float4 along K, store transposed
    const int arow = t >> 2;          // 0..63
    const int acol = (t & 3) * 4;     // 0,4,8,12
    // NN B-tile load indices: float4 along N
    const int brow = t >> 5;          // 0..7
    const int bcol = (t & 31) * 4;    // 0..124

    unsigned long long acc[8][4];
#pragma unroll
    for (int i = 0; i < 8; i++)
#pragma unroll
        for (int j = 0; j < 4; j++) acc[i][j] = 0ULL;

    for (int k0 = 0; k0 < K; k0 += BK) {
#pragma unroll
        for (int p = 0; p < 2; p++) {
            int r = arow + p * 64;
            float4 a = *(const float4*)&A[(size_t)(m0 + r) * K + k0 + acol];
            As[acol + 0][r] = a.x; As[acol + 1][r] = a.y;
            As[acol + 2][r] = a.z; As[acol + 3][r] = a.w;
        }
        if (NT) {
#pragma unroll
            for (int p = 0; p < 2; p++) {
                int r = arow + p * 64;
                float4 b = *(const float4*)&Bm[(size_t)(n0 + r) * K + k0 + acol];
                Bs[acol + 0][r] = b.x; Bs[acol + 1][r] = b.y;
                Bs[acol + 2][r] = b.z; Bs[acol + 3][r] = b.w;
            }
        } else {
#pragma unroll
            for (int p = 0; p < 2; p++) {
                int r = brow + p * 8;
                *(float4*)&Bs[r][bcol] =
                    *(const float4*)&Bm[(size_t)(k0 + r) * N + n0 + bcol];
            }
        }
        __syncthreads();

#pragma unroll
        for (int kk = 0; kk < BK; kk++) {
            float4 a0 = *(const float4*)&As[kk][ty * 8];
            float4 a1 = *(const float4*)&As[kk][ty * 8 + 4];
            const unsigned long long* b64 =
                (const unsigned long long*)&Bs[kk][tx * 8];
            unsigned long long b0 = b64[0], b1 = b64[1], b2 = b64[2], b3 = b64[3];
            float am[8] = {a0.x, a0.y, a0.z, a0.w, a1.x, a1.y, a1.z, a1.w};
#pragma unroll
            for (int i = 0; i < 8; i++) {
                unsigned long long ap = pack2(am[i], am[i]);
                acc[i][0] = fma2(ap, b0, acc[i][0]);
                acc[i][1] = fma2(ap, b1, acc[i][1]);
                acc[i][2] = fma2(ap, b2, acc[i][2]);
                acc[i][3] = fma2(ap, b3, acc[i][3]);
            }
        }
        __syncthreads();
    }

    float bv[8];
#pragma unroll
    for (int j = 0; j < 8; j++) bv[j] = HASBIAS ? bias[n0 + tx * 8 + j] : 0.0f;

#pragma unroll
    for (int i = 0; i < 8; i++) {
        float o[8];
#pragma unroll
        for (int j = 0; j < 4; j++) {
            float lo, hi;
            unpack2(acc[i][j], lo, hi);
            o[2 * j]     = lo * scale + bv[2 * j];
            o[2 * j + 1] = hi * scale + bv[2 * j + 1];
        }
        float* crow = &C[(size_t)(m0 + ty * 8 + i) * N + n0 + tx * 8];
        *(float4*)(crow)     = make_float4(o[0], o[1], o[2], o[3]);
        *(float4*)(crow + 4) = make_float4(o[4], o[5], o[6], o[7]);
    }
}

// ---- row softmax over S=4096 elements, one block/row, 256 threads ----
__global__ void softmax_kernel(float* __restrict__ e)
{
    const int row = blockIdx.x;
    float4* p = (float4*)(e + (size_t)row * Sdim);
    const int t = threadIdx.x;

    float4 v[4];
    float mx = -1e30f;
#pragma unroll
    for (int c = 0; c < 4; c++) {
        v[c] = p[t + c * 256];
        mx = fmaxf(mx, fmaxf(fmaxf(v[c].x, v[c].y), fmaxf(v[c].z, v[c].w)));
    }

    __shared__ float red[256];
    red[t] = mx;
    __syncthreads();
    for (int s = 128; s > 0; s >>= 1) {
        if (t < s) red[t] = fmaxf(red[t], red[t + s]);
        __syncthreads();
    }
    mx = red[0];
    __syncthreads();

    float sum = 0.0f;
#pragma unroll
    for (int c = 0; c < 4; c++) {
        v[c].x = __expf(v[c].x - mx);
        v[c].y = __expf(v[c].y - mx);
        v[c].z = __expf(v[c].z - mx);
        v[c].w = __expf(v[c].w - mx);
        sum += v[c].x + v[c].y + v[c].z + v[c].w;
    }
    red[t] = sum;
    __syncthreads();
    for (int s = 128; s > 0; s >>= 1) {
        if (t < s) red[t] += red[t + s];
        __syncthreads();
    }
    float inv = 1.0f / red[0];
#pragma unroll
    for (int c = 0; c < 4; c++) {
        v[c].x *= inv; v[c].y *= inv; v[c].z *= inv; v[c].w *= inv;
        p[t + c * 256] = v[c];
    }
}

extern "C" void kernel_launch(void* const* d_in, const int* in_sizes, int n_in,
                              void* d_out, int out_size)
{
    const float* x  = (const float*)d_in[0];
    const float* Wq = (const float*)d_in[1];
    const float* bq = (const float*)d_in[2];
    const float* Wk = (const float*)d_in[3];
    const float* bk = (const float*)d_in[4];
    const float* Wv = (const float*)d_in[5];
    const float* bv = (const float*)d_in[6];
    float* out = (float*)d_out;

    float *q, *k, *v, *e;
    cudaGetSymbolAddress((void**)&q, g_q);
    cudaGetSymbolAddress((void**)&k, g_k);
    cudaGetSymbolAddress((void**)&v, g_v);
    cudaGetSymbolAddress((void**)&e, g_e);

    dim3 blk(256);

    // QKV projections: [16384,1024] x [1024,1024] + bias
    dim3 g1(Hdim / 128, Mtot / 128, 1);
    gemm_kernel<false, true><<<g1, blk>>>(x, Wq, bq, q, Mtot, Hdim, Hdim, 0, 0, 0, 1.0f);
    gemm_kernel<false, true><<<g1, blk>>>(x, Wk, bk, k, Mtot, Hdim, Hdim, 0, 0, 0, 1.0f);
    gemm_kernel<false, true><<<g1, blk>>>(x, Wv, bv, v, Mtot, Hdim, Hdim, 0, 0, 0, 1.0f);

    // energy = Q @ K^T / sqrt(H), per batch
    dim3 g2(Sdim / 128, Sdim / 128, Bdim);
    gemm_kernel<true, false><<<g2, blk>>>(q, k, nullptr, e, Sdim, Sdim, Hdim,
                                          (long long)Sdim * Hdim,
                                          (long long)Sdim * Hdim,
                                          (long long)Sdim * Sdim, 1.0f / 32.0f);

    // softmax over last dim
    softmax_kernel<<<Mtot, 256>>>(e);

    // out = attn @ V, per batch
    dim3 g3(Hdim / 128, Sdim / 128, Bdim);
    gemm_kernel<false, false><<<g3, blk>>>(e, v, nullptr, out, Sdim, Hdim, Sdim,
                                           (long long)Sdim * Sdim,
                                           (long long)Sdim * Hdim,
                                           (long long)Sdim * Hdim, 1.0f);
}